// round 13
// baseline (speedup 1.0000x reference)
#include <cuda_runtime.h>
#include <math.h>

#define N_NODES 50000
#define N_EDGES 800000
#define HID     128
#define NGR     512
#define QSD     256       // 2*HID
#define NCLS    10

// ---------------- scratch (device globals; no runtime allocation) ----------------
__device__ int   g_cnt[N_NODES];          // edge-count histogram (zero at load; re-zeroed inside k_fill)
__device__ int   g_rowptr[N_NODES + 1];
__device__ int   g_cursor[N_NODES];
__device__ float g_dis[N_NODES];          // rsqrt(deg incl self-loop)
__device__ int2  g_edges[N_EDGES];        // CSR by target: {src, weight-as-int} (real edges only)
__device__ int   g_gptr[NGR + 1];         // per-graph node ranges (batch sorted)
__device__ float g_hA[N_NODES * HID];
__device__ float g_hB[N_NODES * HID];
__device__ float g_escr[N_NODES];
__device__ float g_WT[384 * 512];         // transposed [Wih|Whh]
__device__ float g_gbias[512];            // bih+bhh

// ---------------- launch 0: degree histogram ----------------
__global__ void k_hist(const int* __restrict__ ei) {
    int e = blockIdx.x * blockDim.x + threadIdx.x;
    if (e < N_EDGES) atomicAdd(&g_cnt[ei[N_EDGES + e]], 1);
}

// ---------------- launch 1: single-block tile-sequential coalesced scan ----------------
__global__ void k_scanfused() {           // <<<1, 1024>>>
    __shared__ int s[1024];
    __shared__ int run_s;
    int tid = threadIdx.x;
    if (tid == 0) run_s = 0;
    __syncthreads();
    for (int t0 = 0; t0 < N_NODES; t0 += 1024) {
        int i = t0 + tid;
        int c = (i < N_NODES) ? g_cnt[i] : 0;
        s[tid] = c;
        __syncthreads();
        for (int off = 1; off < 1024; off <<= 1) {
            int t = (tid >= off) ? s[tid - off] : 0;
            __syncthreads();
            s[tid] += t;
            __syncthreads();
        }
        int incl = s[tid] + run_s;
        if (i < N_NODES) {
            g_rowptr[i + 1] = incl;
            g_cursor[i] = incl - c;
            g_dis[i] = rsqrtf((float)(c + 1));   // normalization includes self-loop
        }
        __syncthreads();                          // everyone has read run_s
        if (tid == 1023) run_s += s[1023];
        __syncthreads();
    }
    if (tid == 0) g_rowptr[0] = 0;
}

// ---------------- launch 2: fill CSR; re-zero g_cnt ----------------
__global__ void k_fill(const int* __restrict__ ei) {
    int idx = blockIdx.x * blockDim.x + threadIdx.x;
    if (idx < N_NODES) g_cnt[idx] = 0;            // restore invariant for next replay
    if (idx >= N_EDGES) return;
    int src = ei[idx], tgt = ei[N_EDGES + idx];
    float w = g_dis[src] * g_dis[tgt];
    int pos = atomicAdd(&g_cursor[tgt], 1);
    g_edges[pos] = make_int2(src, __float_as_int(w));
}

// ---------------- launches 3-5: fused GCN layer: gather -> f32x2 GEMM -> bias+relu ----------------
#define GSTEP(KK, XA, XB, XC, XD)                                              \
    {                                                                          \
        float4 w = W4[(k4 * 4 + KK) * 32 + jg];                                \
        unsigned long long w01, w23, xx;                                       \
        asm("mov.b64 %0,{%1,%2};" : "=l"(w01) : "f"(w.x), "f"(w.y));           \
        asm("mov.b64 %0,{%1,%2};" : "=l"(w23) : "f"(w.z), "f"(w.w));           \
        asm("mov.b64 %0,{%1,%2};" : "=l"(xx) : "f"(XA), "f"(XA));              \
        asm("fma.rn.f32x2 %0,%1,%2,%0;" : "+l"(a0p0) : "l"(xx), "l"(w01));     \
        asm("fma.rn.f32x2 %0,%1,%2,%0;" : "+l"(a0p1) : "l"(xx), "l"(w23));     \
        asm("mov.b64 %0,{%1,%2};" : "=l"(xx) : "f"(XB), "f"(XB));              \
        asm("fma.rn.f32x2 %0,%1,%2,%0;" : "+l"(a1p0) : "l"(xx), "l"(w01));     \
        asm("fma.rn.f32x2 %0,%1,%2,%0;" : "+l"(a1p1) : "l"(xx), "l"(w23));     \
        asm("mov.b64 %0,{%1,%2};" : "=l"(xx) : "f"(XC), "f"(XC));              \
        asm("fma.rn.f32x2 %0,%1,%2,%0;" : "+l"(a2p0) : "l"(xx), "l"(w01));     \
        asm("fma.rn.f32x2 %0,%1,%2,%0;" : "+l"(a2p1) : "l"(xx), "l"(w23));     \
        asm("mov.b64 %0,{%1,%2};" : "=l"(xx) : "f"(XD), "f"(XD));              \
        asm("fma.rn.f32x2 %0,%1,%2,%0;" : "+l"(a3p0) : "l"(xx), "l"(w01));     \
        asm("fma.rn.f32x2 %0,%1,%2,%0;" : "+l"(a3p1) : "l"(xx), "l"(w23));     \
    }

__global__ void __launch_bounds__(256) k_layer(
        const float* __restrict__ in, const float* __restrict__ W,
        const float* __restrict__ bias, float* __restrict__ out) {
    __shared__ float As[32 * 128];
    int tid = threadIdx.x, lane = tid & 31, wp = tid >> 5;
    int r0 = blockIdx.x * 32;
    const float4* in4 = (const float4*)in;
    // ---- gather phase: warp per row, 8-wide edge batching ----
    for (int rr = wp; rr < 32; rr += 8) {
        int i = r0 + rr;
        float4 acc = make_float4(0.f, 0.f, 0.f, 0.f);
        if (i < N_NODES) {
            float di = g_dis[i];
            float sw = di * di;                 // self-loop weight
            float4 sv = in4[i * 32 + lane];
            acc.x = sw * sv.x; acc.y = sw * sv.y; acc.z = sw * sv.z; acc.w = sw * sv.w;
            int s = g_rowptr[i], e = g_rowptr[i + 1];
            int idx = s;
            for (; idx + 8 <= e; idx += 8) {
                int2 e0 = g_edges[idx+0], e1 = g_edges[idx+1];
                int2 e2 = g_edges[idx+2], e3 = g_edges[idx+3];
                int2 e4 = g_edges[idx+4], e5 = g_edges[idx+5];
                int2 e6 = g_edges[idx+6], e7 = g_edges[idx+7];
                float4 v0 = in4[e0.x * 32 + lane];
                float4 v1 = in4[e1.x * 32 + lane];
                float4 v2 = in4[e2.x * 32 + lane];
                float4 v3 = in4[e3.x * 32 + lane];
                float4 v4 = in4[e4.x * 32 + lane];
                float4 v5 = in4[e5.x * 32 + lane];
                float4 v6 = in4[e6.x * 32 + lane];
                float4 v7 = in4[e7.x * 32 + lane];
                float w0 = __int_as_float(e0.y), w1 = __int_as_float(e1.y);
                float w2 = __int_as_float(e2.y), w3 = __int_as_float(e3.y);
                float w4 = __int_as_float(e4.y), w5 = __int_as_float(e5.y);
                float w6 = __int_as_float(e6.y), w7 = __int_as_float(e7.y);
                acc.x += w0*v0.x + w1*v1.x + w2*v2.x + w3*v3.x
                       + w4*v4.x + w5*v5.x + w6*v6.x + w7*v7.x;
                acc.y += w0*v0.y + w1*v1.y + w2*v2.y + w3*v3.y
                       + w4*v4.y + w5*v5.y + w6*v6.y + w7*v7.y;
                acc.z += w0*v0.z + w1*v1.z + w2*v2.z + w3*v3.z
                       + w4*v4.z + w5*v5.z + w6*v6.z + w7*v7.z;
                acc.w += w0*v0.w + w1*v1.w + w2*v2.w + w3*v3.w
                       + w4*v4.w + w5*v5.w + w6*v6.w + w7*v7.w;
            }
            for (; idx < e; idx++) {
                int2 ed = g_edges[idx];
                float wt = __int_as_float(ed.y);
                float4 v = in4[ed.x * 32 + lane];
                acc.x += wt * v.x; acc.y += wt * v.y;
                acc.z += wt * v.z; acc.w += wt * v.w;
            }
        }
        ((float4*)(As + rr * 128))[lane] = acc;
    }
    __syncthreads();
    // ---- GEMM phase: 4 rows x 4 cols per thread, packed f32x2 FMAs ----
    int jg = tid & 31;
    int rg = tid >> 5;
    const float4* W4 = (const float4*)W;
    const float4* A4 = (const float4*)As;
    int rbase = rg * 4;
    unsigned long long a0p0, a0p1, a1p0, a1p1, a2p0, a2p1, a3p0, a3p1;
    {
        float z = 0.f;
        asm("mov.b64 %0,{%1,%1};" : "=l"(a0p0) : "f"(z));
        a0p1 = a0p0; a1p0 = a0p0; a1p1 = a0p0;
        a2p0 = a0p0; a2p1 = a0p0; a3p0 = a0p0; a3p1 = a0p0;
    }
    #pragma unroll 4
    for (int k4 = 0; k4 < 32; k4++) {
        float4 x0 = A4[(rbase + 0) * 32 + k4];
        float4 x1 = A4[(rbase + 1) * 32 + k4];
        float4 x2 = A4[(rbase + 2) * 32 + k4];
        float4 x3 = A4[(rbase + 3) * 32 + k4];
        GSTEP(0, x0.x, x1.x, x2.x, x3.x);
        GSTEP(1, x0.y, x1.y, x2.y, x3.y);
        GSTEP(2, x0.z, x1.z, x2.z, x3.z);
        GSTEP(3, x0.w, x1.w, x2.w, x3.w);
    }
    float4 b = ((const float4*)bias)[jg];
    float4* out4 = (float4*)out;
    int row = r0 + rbase;
    float c0, c1, c2, c3;
    #define EMIT(R, P0, P1)                                                     \
        if (row + R < N_NODES) {                                                \
            asm("mov.b64 {%0,%1},%2;" : "=f"(c0), "=f"(c1) : "l"(P0));          \
            asm("mov.b64 {%0,%1},%2;" : "=f"(c2), "=f"(c3) : "l"(P1));          \
            out4[(row + R) * 32 + jg] = make_float4(                            \
                fmaxf(c0 + b.x, 0.f), fmaxf(c1 + b.y, 0.f),                     \
                fmaxf(c2 + b.z, 0.f), fmaxf(c3 + b.w, 0.f));                    \
        }
    EMIT(0, a0p0, a0p1)
    EMIT(1, a1p0, a1p1)
    EMIT(2, a2p0, a2p1)
    EMIT(3, a3p0, a3p1)
    #undef EMIT
}

// ---------------- launch 6: prep (graph ranges + LSTM weight transpose) ----------------
__global__ void k_prep2(const int* __restrict__ batch,
                        const float* __restrict__ Wih, const float* __restrict__ Whh,
                        const float* __restrict__ bih, const float* __restrict__ bhh) {
    int idx = blockIdx.x * blockDim.x + threadIdx.x;
    if (idx < 384 * 512) {
        int k = idx / 512, j = idx % 512;
        g_WT[idx] = (k < 256) ? Wih[j * 256 + k] : Whh[j * 128 + (k - 256)];
    }
    if (idx < 512) g_gbias[idx] = bih[idx] + bhh[idx];
    if (idx <= NGR) {
        if (idx == NGR) g_gptr[idx] = N_NODES;
        else {
            int lo = 0, hi = N_NODES;
            while (lo < hi) {
                int mid = (lo + hi) >> 1;
                if (batch[mid] < idx) lo = mid + 1; else hi = mid;
            }
            g_gptr[idx] = lo;
        }
    }
}

__device__ __forceinline__ float sigmoidf_(float x) { return 1.f / (1.f + __expf(-x)); }

// ---------------- launch 7: ENTIRE Set2Set (4 steps) + MLP head, one block per graph ----------------
// per-graph LSTM recurrence is independent across graphs -> no cross-block deps.
__global__ void __launch_bounds__(256) k_set2set(
        const float* __restrict__ h,
        const float* __restrict__ L1w, const float* __restrict__ L1b,
        const float* __restrict__ L2w, const float* __restrict__ L2b,
        const float* __restrict__ L3w, const float* __restrict__ L3b,
        float* __restrict__ out) {
    __shared__ float qstar[256];      // [q | r]
    __shared__ float hs_s[128];
    __shared__ float cs_s[128];
    __shared__ float sg[512];         // gate pre-activations
    __shared__ float swmax[8];
    __shared__ float semax;
    __shared__ float sr[256];
    __shared__ float sa[2];
    __shared__ float rfin[128];
    __shared__ float y1[128];
    __shared__ float y2[64];
    __shared__ float ys[NCLS];
    int g = blockIdx.x;
    int tid = threadIdx.x;
    int lane = tid & 31, warp = tid >> 5;
    qstar[tid] = 0.f;
    if (tid < 128) { hs_s[tid] = 0.f; cs_s[tid] = 0.f; }
    __syncthreads();
    int s = g_gptr[g], e = g_gptr[g + 1];
    const float4* h4 = (const float4*)h;

    for (int step = 0; step < 4; step++) {
        // ---- gates GEMM: 512 outputs over 256 threads (2 each), batched W loads ----
        for (int jj = tid; jj < 512; jj += 256) {
            float acc = g_gbias[jj];
            for (int k0 = 0; k0 < 256; k0 += 8) {
                float wv[8];
                #pragma unroll
                for (int u = 0; u < 8; u++) wv[u] = g_WT[(k0 + u) * 512 + jj];
                #pragma unroll
                for (int u = 0; u < 8; u++) acc += qstar[k0 + u] * wv[u];
            }
            for (int k0 = 0; k0 < 128; k0 += 8) {
                float wv[8];
                #pragma unroll
                for (int u = 0; u < 8; u++) wv[u] = g_WT[(256 + k0 + u) * 512 + jj];
                #pragma unroll
                for (int u = 0; u < 8; u++) acc += hs_s[k0 + u] * wv[u];
            }
            sg[jj] = acc;
        }
        __syncthreads();
        // ---- LSTM cell ----
        if (tid < 128) {
            float ig = sg[tid], fg = sg[tid + 128], ga = sg[tid + 256], og = sg[tid + 384];
            float c = sigmoidf_(fg) * cs_s[tid] + sigmoidf_(ig) * tanhf(ga);
            cs_s[tid] = c;
            float q = sigmoidf_(og) * tanhf(c);
            hs_s[tid] = q;
            qstar[tid] = q;
        }
        __syncthreads();
        // ---- attention (per-block uniform branch on empty graph) ----
        if (s < e) {
            float lmax = -INFINITY;
            float4 qv = ((const float4*)hs_s)[lane];
            for (int i = s + warp; i < e; i += 8) {
                float4 hv = h4[i * 32 + lane];
                float d = hv.x * qv.x + hv.y * qv.y + hv.z * qv.z + hv.w * qv.w;
                #pragma unroll
                for (int o = 16; o > 0; o >>= 1) d += __shfl_xor_sync(0xffffffffu, d, o);
                if (lane == 0) g_escr[i] = d;
                lmax = fmaxf(lmax, d);
            }
            if (lane == 0) swmax[warp] = lmax;
            __syncthreads();
            if (tid == 0) {
                float m = swmax[0];
                #pragma unroll
                for (int w = 1; w < 8; w++) m = fmaxf(m, swmax[w]);
                semax = m;
            }
            __syncthreads();
            float emax = semax;
            int grp = tid >> 7, dim = tid & 127;
            int half = (e - s) >> 1;
            int b0 = (grp == 0) ? s : s + half;
            int b1 = (grp == 0) ? s + half : e;
            float r = 0.f, asum = 0.f;
            #pragma unroll 4
            for (int i = b0; i < b1; i++) {
                float w = __expf(g_escr[i] - emax);
                asum += w;
                r += w * h[i * 128 + dim];
            }
            sr[tid] = r;
            if (dim == 0) sa[grp] = asum;
            __syncthreads();
            if (tid < 128) {
                float rt = sr[tid] + sr[128 + tid];
                float at = sa[0] + sa[1];
                rfin[tid] = rt / (at > 0.f ? at : 1.f);
            }
        } else {
            if (tid < 128) rfin[tid] = 0.f;
        }
        __syncthreads();
        if (tid < 128) qstar[128 + tid] = rfin[tid];
        __syncthreads();
    }

    // ---- MLP head + log_softmax ----
    if (tid < 128) {
        float acc = L1b[tid];
        #pragma unroll 4
        for (int k = 0; k < 128; k++) acc += hs_s[k] * L1w[k * 128 + tid];
        #pragma unroll 4
        for (int k = 0; k < 128; k++) acc += rfin[k] * L1w[(128 + k) * 128 + tid];
        y1[tid] = fmaxf(acc, 0.f);
    }
    __syncthreads();
    if (tid < 64) {
        float acc = L2b[tid];
        #pragma unroll 4
        for (int k = 0; k < 128; k++) acc += y1[k] * L2w[k * 64 + tid];
        y2[tid] = fmaxf(acc, 0.f);
    }
    __syncthreads();
    if (tid < NCLS) {
        float acc = L3b[tid];
        #pragma unroll
        for (int k = 0; k < 64; k++) acc += y2[k] * L3w[k * NCLS + tid];
        ys[tid] = acc;
    }
    __syncthreads();
    if (tid < NCLS) {
        float m = ys[0];
        #pragma unroll
        for (int k = 1; k < NCLS; k++) m = fmaxf(m, ys[k]);
        float se = 0.f;
        #pragma unroll
        for (int k = 0; k < NCLS; k++) se += expf(ys[k] - m);
        out[g * NCLS + tid] = ys[tid] - m - logf(se);
    }
}

// ---------------- launcher ----------------
extern "C" void kernel_launch(void* const* d_in, const int* in_sizes, int n_in,
                              void* d_out, int out_size) {
    const float* x     = (const float*)d_in[0];
    const int*   ei    = (const int*)  d_in[1];
    const int*   batch = (const int*)  d_in[2];
    const float* W1 = (const float*)d_in[3];  const float* b1 = (const float*)d_in[4];
    const float* W2 = (const float*)d_in[5];  const float* b2 = (const float*)d_in[6];
    const float* W3 = (const float*)d_in[7];  const float* b3 = (const float*)d_in[8];
    const float* Wih = (const float*)d_in[9]; const float* Whh = (const float*)d_in[10];
    const float* bih = (const float*)d_in[11];const float* bhh = (const float*)d_in[12];
    const float* L1w = (const float*)d_in[13];const float* L1b = (const float*)d_in[14];
    const float* L2w = (const float*)d_in[15];const float* L2b = (const float*)d_in[16];
    const float* L3w = (const float*)d_in[17];const float* L3b = (const float*)d_in[18];
    float* out = (float*)d_out;

    int layer_grid = (N_NODES + 31) / 32;

    k_hist<<<(N_EDGES + 255) / 256, 256>>>(ei);                           // 0
    k_scanfused<<<1, 1024>>>();                                           // 1
    k_fill<<<(N_EDGES + 255) / 256, 256>>>(ei);                           // 2

    k_layer<<<layer_grid, 256>>>(x,    W1, b1, g_hA);                     // 3  <- ncu capture (f32x2 A/B)
    k_layer<<<layer_grid, 256>>>(g_hA, W2, b2, g_hB);                     // 4
    k_layer<<<layer_grid, 256>>>(g_hB, W3, b3, g_hA);                     // 5

    k_prep2<<<(384 * 512 + 255) / 256, 256>>>(batch, Wih, Whh, bih, bhh); // 6
    k_set2set<<<NGR, 256>>>(g_hA, L1w, L1b, L2w, L2b, L3w, L3b, out);     // 7
}

// round 14
// speedup vs baseline: 1.0448x; 1.0448x over previous
#include <cuda_runtime.h>
#include <math.h>

#define N_NODES 50000
#define N_EDGES 800000
#define HID     128
#define NGR     512
#define QSD     256       // 2*HID
#define NCLS    10
#define SCAN_NB 49        // ceil(50000/1024)

// ---------------- scratch (device globals; no runtime allocation) ----------------
__device__ int   g_cnt[N_NODES];          // edge-count histogram (zero at load; re-zeroed inside k_fill)
__device__ int   g_rowptr[N_NODES + 1];
__device__ int   g_cursor[N_NODES];
__device__ float g_dis[N_NODES];          // rsqrt(deg incl self-loop)
__device__ int   g_incl[SCAN_NB * 1024];  // block-local inclusive scan
__device__ int   g_bsums[SCAN_NB];
__device__ int2  g_edges[N_EDGES];        // CSR by target: {src, weight-as-int} (real edges only)
__device__ int   g_gptr[NGR + 1];         // per-graph node ranges (batch sorted)
__device__ float g_hA[N_NODES * HID];
__device__ float g_hB[N_NODES * HID];
__device__ float g_escr[N_NODES];
__device__ float g_WT[384 * 512];         // transposed [Wih|Whh]
__device__ float g_gbias[512];            // bih+bhh
__device__ float g_hs[NGR * HID];
__device__ float g_cs[NGR * HID];
__device__ float g_qstar[NGR * QSD];

// ---------------- launch 0: degree histogram ----------------
__global__ void k_hist(const int* __restrict__ ei) {
    int e = blockIdx.x * blockDim.x + threadIdx.x;
    if (e < N_EDGES) atomicAdd(&g_cnt[ei[N_EDGES + e]], 1);
}

// ---------------- launch 1: per-block inclusive scan (coalesced) ----------------
__global__ void k_scanA() {               // <<<SCAN_NB, 1024>>>
    __shared__ int s[1024];
    int tid = threadIdx.x;
    int i = blockIdx.x * 1024 + tid;
    int v = (i < N_NODES) ? g_cnt[i] : 0;
    s[tid] = v;
    __syncthreads();
    for (int off = 1; off < 1024; off <<= 1) {
        int t = (tid >= off) ? s[tid - off] : 0;
        __syncthreads();
        s[tid] += t;
        __syncthreads();
    }
    g_incl[blockIdx.x * 1024 + tid] = s[tid];
    if (tid == 1023) g_bsums[blockIdx.x] = s[1023];
}

// ---------------- launch 4: scan fix-up -> rowptr, cursor, dis (coalesced) ----------------
__global__ void k_scanB() {               // <<<SCAN_NB, 1024>>>
    __shared__ int soff;
    int tid = threadIdx.x;
    int b = blockIdx.x;
    if (tid == 0) {
        int o = 0;
        for (int j = 0; j < b; j++) o += g_bsums[j];
        soff = o;
    }
    __syncthreads();
    int i = b * 1024 + tid;
    if (i < N_NODES) {
        int incl = g_incl[i] + soff;
        int c = g_cnt[i];
        g_rowptr[i + 1] = incl;
        g_cursor[i] = incl - c;
        g_dis[i] = rsqrtf((float)(c + 1));   // normalization includes self-loop
    }
    if (i == 0) g_rowptr[0] = 0;
}

// ---------------- launch 2: set2set prep (states + graph ranges + LSTM weight transpose) ----------------
__global__ void k_prep2(const int* __restrict__ batch,
                        const float* __restrict__ Wih, const float* __restrict__ Whh,
                        const float* __restrict__ bih, const float* __restrict__ bhh) {
    int idx = blockIdx.x * blockDim.x + threadIdx.x;
    if (idx < 384 * 512) {
        int k = idx / 512, j = idx % 512;
        g_WT[idx] = (k < 256) ? Wih[j * 256 + k] : Whh[j * 128 + (k - 256)];
    }
    if (idx < 512) g_gbias[idx] = bih[idx] + bhh[idx];
    if (idx < NGR * HID) { g_hs[idx] = 0.f; g_cs[idx] = 0.f; }
    if (idx < NGR * QSD) g_qstar[idx] = 0.f;
    if (idx <= NGR) {
        if (idx == NGR) g_gptr[idx] = N_NODES;
        else {
            int lo = 0, hi = N_NODES;
            while (lo < hi) {
                int mid = (lo + hi) >> 1;
                if (batch[mid] < idx) lo = mid + 1; else hi = mid;
            }
            g_gptr[idx] = lo;
        }
    }
}

// ---------------- launch 5: fill CSR; re-zero g_cnt ----------------
__global__ void k_fill(const int* __restrict__ ei) {
    int idx = blockIdx.x * blockDim.x + threadIdx.x;
    if (idx < N_NODES) g_cnt[idx] = 0;            // restore invariant for next replay
    if (idx >= N_EDGES) return;
    int src = ei[idx], tgt = ei[N_EDGES + idx];
    float w = g_dis[src] * g_dis[tgt];
    int pos = atomicAdd(&g_cursor[tgt], 1);
    g_edges[pos] = make_int2(src, __float_as_int(w));
}

// ---------------- fused GCN layer: pipelined gather -> f32x2 GEMM -> bias+relu ----------------
#define GSTEP(KK, XA, XB, XC, XD)                                              \
    {                                                                          \
        float4 w = W4[(k4 * 4 + KK) * 32 + jg];                                \
        unsigned long long w01, w23, xx;                                       \
        asm("mov.b64 %0,{%1,%2};" : "=l"(w01) : "f"(w.x), "f"(w.y));           \
        asm("mov.b64 %0,{%1,%2};" : "=l"(w23) : "f"(w.z), "f"(w.w));           \
        asm("mov.b64 %0,{%1,%2};" : "=l"(xx) : "f"(XA), "f"(XA));              \
        asm("fma.rn.f32x2 %0,%1,%2,%0;" : "+l"(a0p0) : "l"(xx), "l"(w01));     \
        asm("fma.rn.f32x2 %0,%1,%2,%0;" : "+l"(a0p1) : "l"(xx), "l"(w23));     \
        asm("mov.b64 %0,{%1,%2};" : "=l"(xx) : "f"(XB), "f"(XB));              \
        asm("fma.rn.f32x2 %0,%1,%2,%0;" : "+l"(a1p0) : "l"(xx), "l"(w01));     \
        asm("fma.rn.f32x2 %0,%1,%2,%0;" : "+l"(a1p1) : "l"(xx), "l"(w23));     \
        asm("mov.b64 %0,{%1,%2};" : "=l"(xx) : "f"(XC), "f"(XC));              \
        asm("fma.rn.f32x2 %0,%1,%2,%0;" : "+l"(a2p0) : "l"(xx), "l"(w01));     \
        asm("fma.rn.f32x2 %0,%1,%2,%0;" : "+l"(a2p1) : "l"(xx), "l"(w23));     \
        asm("mov.b64 %0,{%1,%2};" : "=l"(xx) : "f"(XD), "f"(XD));              \
        asm("fma.rn.f32x2 %0,%1,%2,%0;" : "+l"(a3p0) : "l"(xx), "l"(w01));     \
        asm("fma.rn.f32x2 %0,%1,%2,%0;" : "+l"(a3p1) : "l"(xx), "l"(w23));     \
    }

// consume one 8-edge batch held in eb0..eb7
#define CONSUME8()                                                              \
    {                                                                           \
        float4 v0 = in4[eb0.x * 32 + lane];                                     \
        float4 v1 = in4[eb1.x * 32 + lane];                                     \
        float4 v2 = in4[eb2.x * 32 + lane];                                     \
        float4 v3 = in4[eb3.x * 32 + lane];                                     \
        float4 v4 = in4[eb4.x * 32 + lane];                                     \
        float4 v5 = in4[eb5.x * 32 + lane];                                     \
        float4 v6 = in4[eb6.x * 32 + lane];                                     \
        float4 v7 = in4[eb7.x * 32 + lane];                                     \
        float w0 = __int_as_float(eb0.y), w1 = __int_as_float(eb1.y);           \
        float w2 = __int_as_float(eb2.y), w3 = __int_as_float(eb3.y);           \
        float w4 = __int_as_float(eb4.y), w5 = __int_as_float(eb5.y);           \
        float w6 = __int_as_float(eb6.y), w7 = __int_as_float(eb7.y);           \
        acc.x += w0*v0.x + w1*v1.x + w2*v2.x + w3*v3.x                          \
               + w4*v4.x + w5*v5.x + w6*v6.x + w7*v7.x;                         \
        acc.y += w0*v0.y + w1*v1.y + w2*v2.y + w3*v3.y                          \
               + w4*v4.y + w5*v5.y + w6*v6.y + w7*v7.y;                         \
        acc.z += w0*v0.z + w1*v1.z + w2*v2.z + w3*v3.z                          \
               + w4*v4.z + w5*v5.z + w6*v6.z + w7*v7.z;                         \
        acc.w += w0*v0.w + w1*v1.w + w2*v2.w + w3*v3.w                          \
               + w4*v4.w + w5*v5.w + w6*v6.w + w7*v7.w;                         \
    }

__global__ void __launch_bounds__(256) k_layer(
        const float* __restrict__ in, const float* __restrict__ W,
        const float* __restrict__ bias, float* __restrict__ out) {
    __shared__ float As[32 * 128];
    int tid = threadIdx.x, lane = tid & 31, wp = tid >> 5;
    int r0 = blockIdx.x * 32;
    const float4* in4 = (const float4*)in;
    // ---- gather phase: warp per row, double-buffered 8-wide edge batches ----
    for (int rr = wp; rr < 32; rr += 8) {
        int i = r0 + rr;
        float4 acc = make_float4(0.f, 0.f, 0.f, 0.f);
        if (i < N_NODES) {
            float di = g_dis[i];
            float sw = di * di;                 // self-loop weight
            float4 sv = in4[i * 32 + lane];
            acc.x = sw * sv.x; acc.y = sw * sv.y; acc.z = sw * sv.z; acc.w = sw * sv.w;
            int s = g_rowptr[i], e = g_rowptr[i + 1];
            int idx = s;
            int end8 = s + ((e - s) & ~7);
            if (idx < end8) {
                int2 eb0 = g_edges[idx+0], eb1 = g_edges[idx+1];
                int2 eb2 = g_edges[idx+2], eb3 = g_edges[idx+3];
                int2 eb4 = g_edges[idx+4], eb5 = g_edges[idx+5];
                int2 eb6 = g_edges[idx+6], eb7 = g_edges[idx+7];
                idx += 8;
                for (; idx < end8; idx += 8) {
                    // prefetch next batch (independent -> overlaps with CONSUME8's loads)
                    int2 n0 = g_edges[idx+0], n1 = g_edges[idx+1];
                    int2 n2 = g_edges[idx+2], n3 = g_edges[idx+3];
                    int2 n4 = g_edges[idx+4], n5 = g_edges[idx+5];
                    int2 n6 = g_edges[idx+6], n7 = g_edges[idx+7];
                    CONSUME8();
                    eb0 = n0; eb1 = n1; eb2 = n2; eb3 = n3;
                    eb4 = n4; eb5 = n5; eb6 = n6; eb7 = n7;
                }
                CONSUME8();   // drain last full batch
            }
            for (; idx < e; idx++) {
                int2 ed = g_edges[idx];
                float wt = __int_as_float(ed.y);
                float4 v = in4[ed.x * 32 + lane];
                acc.x += wt * v.x; acc.y += wt * v.y;
                acc.z += wt * v.z; acc.w += wt * v.w;
            }
        }
        ((float4*)(As + rr * 128))[lane] = acc;
    }
    __syncthreads();
    // ---- GEMM phase: 4 rows x 4 cols per thread, packed f32x2 FMAs ----
    int jg = tid & 31;
    int rg = tid >> 5;
    const float4* W4 = (const float4*)W;
    const float4* A4 = (const float4*)As;
    int rbase = rg * 4;
    unsigned long long a0p0, a0p1, a1p0, a1p1, a2p0, a2p1, a3p0, a3p1;
    {
        float z = 0.f;
        asm("mov.b64 %0,{%1,%1};" : "=l"(a0p0) : "f"(z));
        a0p1 = a0p0; a1p0 = a0p0; a1p1 = a0p0;
        a2p0 = a0p0; a2p1 = a0p0; a3p0 = a0p0; a3p1 = a0p0;
    }
    #pragma unroll 4
    for (int k4 = 0; k4 < 32; k4++) {
        float4 x0 = A4[(rbase + 0) * 32 + k4];
        float4 x1 = A4[(rbase + 1) * 32 + k4];
        float4 x2 = A4[(rbase + 2) * 32 + k4];
        float4 x3 = A4[(rbase + 3) * 32 + k4];
        GSTEP(0, x0.x, x1.x, x2.x, x3.x);
        GSTEP(1, x0.y, x1.y, x2.y, x3.y);
        GSTEP(2, x0.z, x1.z, x2.z, x3.z);
        GSTEP(3, x0.w, x1.w, x2.w, x3.w);
    }
    float4 b = ((const float4*)bias)[jg];
    float4* out4 = (float4*)out;
    int row = r0 + rbase;
    float c0, c1, c2, c3;
    #define EMIT(R, P0, P1)                                                     \
        if (row + R < N_NODES) {                                                \
            asm("mov.b64 {%0,%1},%2;" : "=f"(c0), "=f"(c1) : "l"(P0));          \
            asm("mov.b64 {%0,%1},%2;" : "=f"(c2), "=f"(c3) : "l"(P1));          \
            out4[(row + R) * 32 + jg] = make_float4(                            \
                fmaxf(c0 + b.x, 0.f), fmaxf(c1 + b.y, 0.f),                     \
                fmaxf(c2 + b.z, 0.f), fmaxf(c3 + b.w, 0.f));                    \
        }
    EMIT(0, a0p0, a0p1)
    EMIT(1, a1p0, a1p1)
    EMIT(2, a2p0, a2p1)
    EMIT(3, a3p0, a3p1)
    #undef EMIT
}

__device__ __forceinline__ float sigmoidf_(float x) { return 1.f / (1.f + __expf(-x)); }

// ---------------- fused LSTM-gates GEMM + nonlinearity (2 graphs / block, 256 blocks) ----------------
__global__ void __launch_bounds__(512) k_gates_lstm() {
    __shared__ float sA[2 * 384];     // [q_star | hs] inputs
    __shared__ float sg[2 * 512];     // gate pre-activations
    int tid = threadIdx.x;
    int gb = blockIdx.x;              // 0..255
    for (int idx = tid; idx < 2 * 384; idx += 512) {
        int g = idx / 384, k = idx % 384;
        int gg = gb * 2 + g;
        sA[idx] = (k < 256) ? g_qstar[gg * 256 + k] : g_hs[gg * 128 + (k - 256)];
    }
    __syncthreads();
    int j = tid;                      // 0..511 gate index
    float acc0 = 0.f, acc1 = 0.f;
    for (int k0 = 0; k0 < 384; k0 += 8) {
        float wv[8];
        #pragma unroll
        for (int u = 0; u < 8; u++) wv[u] = g_WT[(k0 + u) * 512 + j];
        #pragma unroll
        for (int u = 0; u < 8; u++) {
            acc0 += sA[k0 + u]       * wv[u];
            acc1 += sA[384 + k0 + u] * wv[u];
        }
    }
    float bb = g_gbias[j];
    sg[j]       = acc0 + bb;
    sg[512 + j] = acc1 + bb;
    __syncthreads();
    // LSTM cell update: 2 graphs x 128 dims = 256 items
    if (tid < 256) {
        int g = tid >> 7, jj = tid & 127;
        int gg = gb * 2 + g;
        const float* gr = &sg[g * 512];
        float ig = gr[jj], fg = gr[jj + 128], ga = gr[jj + 256], og = gr[jj + 384];
        int gidx = gg * 128 + jj;
        float c = sigmoidf_(fg) * g_cs[gidx] + sigmoidf_(ig) * tanhf(ga);
        g_cs[gidx] = c;
        float q = sigmoidf_(og) * tanhf(c);
        g_hs[gidx] = q;
        g_qstar[gg * 256 + jj] = q;   // q part of q_star
    }
}

// ---------------- attention (+ fused MLP head on the last step), block per graph ----------------
__global__ void __launch_bounds__(256) k_attn(
        const float* __restrict__ h, int do_mlp,
        const float* __restrict__ L1w, const float* __restrict__ L1b,
        const float* __restrict__ L2w, const float* __restrict__ L2b,
        const float* __restrict__ L3w, const float* __restrict__ L3b,
        float* __restrict__ out) {
    __shared__ float sq[128];
    __shared__ float swmax[8];
    __shared__ float semax;
    __shared__ float sr[256];
    __shared__ float sa[2];
    __shared__ float rfin[128];
    __shared__ float y1[128];
    __shared__ float y2[64];
    __shared__ float ys[NCLS];
    int g = blockIdx.x;
    int tid = threadIdx.x;
    int lane = tid & 31, warp = tid >> 5;
    if (tid < 128) sq[tid] = g_hs[g * 128 + tid];
    __syncthreads();
    int s = g_gptr[g], e = g_gptr[g + 1];
    if (s < e) {
        float lmax = -INFINITY;
        float4 qv = ((const float4*)sq)[lane];
        const float4* h4 = (const float4*)h;
        for (int i = s + warp; i < e; i += 8) {
            float4 hv = h4[i * 32 + lane];
            float d = hv.x * qv.x + hv.y * qv.y + hv.z * qv.z + hv.w * qv.w;
            #pragma unroll
            for (int o = 16; o > 0; o >>= 1) d += __shfl_xor_sync(0xffffffffu, d, o);
            if (lane == 0) g_escr[i] = d;
            lmax = fmaxf(lmax, d);
        }
        if (lane == 0) swmax[warp] = lmax;
        __syncthreads();
        if (tid == 0) {
            float m = swmax[0];
            #pragma unroll
            for (int w = 1; w < 8; w++) m = fmaxf(m, swmax[w]);
            semax = m;
        }
        __syncthreads();
        float emax = semax;
        int grp = tid >> 7, dim = tid & 127;
        int half = (e - s) >> 1;
        int b0 = (grp == 0) ? s : s + half;
        int b1 = (grp == 0) ? s + half : e;
        float r = 0.f, asum = 0.f;
        #pragma unroll 4
        for (int i = b0; i < b1; i++) {
            float w = __expf(g_escr[i] - emax);
            asum += w;
            r += w * h[i * 128 + dim];
        }
        sr[tid] = r;
        if (dim == 0) sa[grp] = asum;
        __syncthreads();
        if (tid < 128) {
            float rt = sr[tid] + sr[128 + tid];
            float at = sa[0] + sa[1];
            rfin[tid] = rt / (at > 0.f ? at : 1.f);
        }
    } else {
        if (tid < 128) rfin[tid] = 0.f;
    }
    __syncthreads();
    if (!do_mlp) {
        if (tid < 128) g_qstar[g * 256 + 128 + tid] = rfin[tid];
        return;
    }
    if (tid < 128) {
        float acc = L1b[tid];
        #pragma unroll 4
        for (int k = 0; k < 128; k++) acc += sq[k] * L1w[k * 128 + tid];
        #pragma unroll 4
        for (int k = 0; k < 128; k++) acc += rfin[k] * L1w[(128 + k) * 128 + tid];
        y1[tid] = fmaxf(acc, 0.f);
    }
    __syncthreads();
    if (tid < 64) {
        float acc = L2b[tid];
        #pragma unroll 4
        for (int k = 0; k < 128; k++) acc += y1[k] * L2w[k * 64 + tid];
        y2[tid] = fmaxf(acc, 0.f);
    }
    __syncthreads();
    if (tid < NCLS) {
        float acc = L3b[tid];
        #pragma unroll
        for (int k = 0; k < 64; k++) acc += y2[k] * L3w[k * NCLS + tid];
        ys[tid] = acc;
    }
    __syncthreads();
    if (tid < NCLS) {
        float m = ys[0];
        #pragma unroll
        for (int k = 1; k < NCLS; k++) m = fmaxf(m, ys[k]);
        float se = 0.f;
        #pragma unroll
        for (int k = 0; k < NCLS; k++) se += expf(ys[k] - m);
        out[g * NCLS + tid] = ys[tid] - m - logf(se);
    }
}

// ---------------- launcher ----------------
extern "C" void kernel_launch(void* const* d_in, const int* in_sizes, int n_in,
                              void* d_out, int out_size) {
    const float* x     = (const float*)d_in[0];
    const int*   ei    = (const int*)  d_in[1];
    const int*   batch = (const int*)  d_in[2];
    const float* W1 = (const float*)d_in[3];  const float* b1 = (const float*)d_in[4];
    const float* W2 = (const float*)d_in[5];  const float* b2 = (const float*)d_in[6];
    const float* W3 = (const float*)d_in[7];  const float* b3 = (const float*)d_in[8];
    const float* Wih = (const float*)d_in[9]; const float* Whh = (const float*)d_in[10];
    const float* bih = (const float*)d_in[11];const float* bhh = (const float*)d_in[12];
    const float* L1w = (const float*)d_in[13];const float* L1b = (const float*)d_in[14];
    const float* L2w = (const float*)d_in[15];const float* L2b = (const float*)d_in[16];
    const float* L3w = (const float*)d_in[17];const float* L3b = (const float*)d_in[18];
    float* out = (float*)d_out;

    int layer_grid = (N_NODES + 31) / 32;

    k_hist<<<(N_EDGES + 255) / 256, 256>>>(ei);                           // 0
    k_scanA<<<SCAN_NB, 1024>>>();                                         // 1
    k_prep2<<<(384 * 512 + 255) / 256, 256>>>(batch, Wih, Whh, bih, bhh); // 2
    k_gates_lstm<<<256, 512>>>();                                         // 3  <- ncu capture (step 0)
    k_scanB<<<SCAN_NB, 1024>>>();                                         // 4
    k_fill<<<(N_EDGES + 255) / 256, 256>>>(ei);                           // 5

    k_layer<<<layer_grid, 256>>>(x,    W1, b1, g_hA);                     // 6
    k_layer<<<layer_grid, 256>>>(g_hA, W2, b2, g_hB);                     // 7
    k_layer<<<layer_grid, 256>>>(g_hB, W3, b3, g_hA);                     // 8

    k_attn<<<NGR, 256>>>(g_hA, 0, L1w, L1b, L2w, L2b, L3w, L3b, out);     // 9 (step 0 attn)
    for (int step = 1; step < 4; step++) {
        k_gates_lstm<<<256, 512>>>();
        k_attn<<<NGR, 256>>>(g_hA, step == 3 ? 1 : 0,
                             L1w, L1b, L2w, L2b, L3w, L3b, out);
    }
}

// round 16
// speedup vs baseline: 1.0506x; 1.0056x over previous
#include <cuda_runtime.h>
#include <math.h>

#define N_NODES 50000
#define N_EDGES 800000
#define HID     128
#define NGR     512
#define QSD     256       // 2*HID
#define NCLS    10
#define SCAN_NB 49        // ceil(50000/1024)

// ---------------- scratch (device globals; no runtime allocation) ----------------
__device__ int   g_cnt[N_NODES];          // edge-count histogram (zero at load; re-zeroed inside k_fill)
__device__ int   g_rowptr[N_NODES + 1];
__device__ int   g_cursor[N_NODES];
__device__ float g_dis[N_NODES];          // rsqrt(deg incl self-loop)
__device__ int   g_incl[SCAN_NB * 1024];  // block-local inclusive scan
__device__ int   g_bsums[SCAN_NB];
__device__ int2  g_edges[N_EDGES];        // CSR by target: {src, weight-as-int} (real edges only)
__device__ int   g_gptr[NGR + 1];         // per-graph node ranges (batch sorted)
__device__ float g_hA[N_NODES * HID];
__device__ float g_hB[N_NODES * HID];
__device__ float g_escr[N_NODES];
__device__ float g_WT[384 * 512];         // transposed [Wih|Whh]
__device__ float g_gbias[512];            // bih+bhh
__device__ float g_hs[NGR * HID];
__device__ float g_cs[NGR * HID];
__device__ float g_qstar[NGR * QSD];

// ---------------- launch 0: degree histogram ----------------
__global__ void k_hist(const int* __restrict__ ei) {
    int e = blockIdx.x * blockDim.x + threadIdx.x;
    if (e < N_EDGES) atomicAdd(&g_cnt[ei[N_EDGES + e]], 1);
}

// ---------------- launch 1: per-block inclusive scan (coalesced) ----------------
__global__ void k_scanA() {               // <<<SCAN_NB, 1024>>>
    __shared__ int s[1024];
    int tid = threadIdx.x;
    int i = blockIdx.x * 1024 + tid;
    int v = (i < N_NODES) ? g_cnt[i] : 0;
    s[tid] = v;
    __syncthreads();
    for (int off = 1; off < 1024; off <<= 1) {
        int t = (tid >= off) ? s[tid - off] : 0;
        __syncthreads();
        s[tid] += t;
        __syncthreads();
    }
    g_incl[blockIdx.x * 1024 + tid] = s[tid];
    if (tid == 1023) g_bsums[blockIdx.x] = s[1023];
}

// ---------------- launch 4: scan fix-up -> rowptr, cursor, dis (coalesced) ----------------
__global__ void k_scanB() {               // <<<SCAN_NB, 1024>>>
    __shared__ int soff;
    int tid = threadIdx.x;
    int b = blockIdx.x;
    if (tid == 0) {
        int o = 0;
        for (int j = 0; j < b; j++) o += g_bsums[j];
        soff = o;
    }
    __syncthreads();
    int i = b * 1024 + tid;
    if (i < N_NODES) {
        int incl = g_incl[i] + soff;
        int c = g_cnt[i];
        g_rowptr[i + 1] = incl;
        g_cursor[i] = incl - c;
        g_dis[i] = rsqrtf((float)(c + 1));   // normalization includes self-loop
    }
    if (i == 0) g_rowptr[0] = 0;
}

// ---------------- launch 2: set2set prep (states + graph ranges + LSTM weight transpose) ----------------
__global__ void k_prep2(const int* __restrict__ batch,
                        const float* __restrict__ Wih, const float* __restrict__ Whh,
                        const float* __restrict__ bih, const float* __restrict__ bhh) {
    int idx = blockIdx.x * blockDim.x + threadIdx.x;
    if (idx < 384 * 512) {
        int k = idx / 512, j = idx % 512;
        g_WT[idx] = (k < 256) ? Wih[j * 256 + k] : Whh[j * 128 + (k - 256)];
    }
    if (idx < 512) g_gbias[idx] = bih[idx] + bhh[idx];
    if (idx < NGR * HID) { g_hs[idx] = 0.f; g_cs[idx] = 0.f; }
    if (idx < NGR * QSD) g_qstar[idx] = 0.f;
    if (idx <= NGR) {
        if (idx == NGR) g_gptr[idx] = N_NODES;
        else {
            int lo = 0, hi = N_NODES;
            while (lo < hi) {
                int mid = (lo + hi) >> 1;
                if (batch[mid] < idx) lo = mid + 1; else hi = mid;
            }
            g_gptr[idx] = lo;
        }
    }
}

// ---------------- launch 5: fill CSR; re-zero g_cnt ----------------
__global__ void k_fill(const int* __restrict__ ei) {
    int idx = blockIdx.x * blockDim.x + threadIdx.x;
    if (idx < N_NODES) g_cnt[idx] = 0;            // restore invariant for next replay
    if (idx >= N_EDGES) return;
    int src = ei[idx], tgt = ei[N_EDGES + idx];
    float w = g_dis[src] * g_dis[tgt];
    int pos = atomicAdd(&g_cursor[tgt], 1);
    g_edges[pos] = make_int2(src, __float_as_int(w));
}

// ---------------- fused GCN layer: one-row-per-warp gather -> f32x2 GEMM -> bias+relu ----------------
// consume one 8-edge batch held in eb0..eb7
#define CONSUME8()                                                              \
    {                                                                           \
        float4 v0 = in4[eb0.x * 32 + lane];                                     \
        float4 v1 = in4[eb1.x * 32 + lane];                                     \
        float4 v2 = in4[eb2.x * 32 + lane];                                     \
        float4 v3 = in4[eb3.x * 32 + lane];                                     \
        float4 v4 = in4[eb4.x * 32 + lane];                                     \
        float4 v5 = in4[eb5.x * 32 + lane];                                     \
        float4 v6 = in4[eb6.x * 32 + lane];                                     \
        float4 v7 = in4[eb7.x * 32 + lane];                                     \
        float w0 = __int_as_float(eb0.y), w1 = __int_as_float(eb1.y);           \
        float w2 = __int_as_float(eb2.y), w3 = __int_as_float(eb3.y);           \
        float w4 = __int_as_float(eb4.y), w5 = __int_as_float(eb5.y);           \
        float w6 = __int_as_float(eb6.y), w7 = __int_as_float(eb7.y);           \
        acc.x += w0*v0.x + w1*v1.x + w2*v2.x + w3*v3.x                          \
               + w4*v4.x + w5*v5.x + w6*v6.x + w7*v7.x;                         \
        acc.y += w0*v0.y + w1*v1.y + w2*v2.y + w3*v3.y                          \
               + w4*v4.y + w5*v5.y + w6*v6.y + w7*v7.y;                         \
        acc.z += w0*v0.z + w1*v1.z + w2*v2.z + w3*v3.z                          \
               + w4*v4.z + w5*v5.z + w6*v6.z + w7*v7.z;                         \
        acc.w += w0*v0.w + w1*v1.w + w2*v2.w + w3*v3.w                          \
               + w4*v4.w + w5*v5.w + w6*v6.w + w7*v7.w;                         \
    }

__global__ void __launch_bounds__(256) k_layer(
        const float* __restrict__ in, const float* __restrict__ W,
        const float* __restrict__ bias, float* __restrict__ out) {
    __shared__ float As[8 * 128];             // 8 rows x 128 features
    int tid = threadIdx.x, lane = tid & 31, wp = tid >> 5;
    int r0 = blockIdx.x * 8;
    const float4* in4 = (const float4*)in;
    // ---- gather phase: ONE row per warp (short critical path), 8-wide batches + prefetch ----
    {
        int i = r0 + wp;                       // grid sized so i < N_NODES always
        float4 acc;
        float di = g_dis[i];
        float sw = di * di;                    // self-loop weight
        float4 sv = in4[i * 32 + lane];
        acc.x = sw * sv.x; acc.y = sw * sv.y; acc.z = sw * sv.z; acc.w = sw * sv.w;
        int s = g_rowptr[i], e = g_rowptr[i + 1];
        int idx = s;
        int end8 = s + ((e - s) & ~7);
        if (idx < end8) {
            int2 eb0 = g_edges[idx+0], eb1 = g_edges[idx+1];
            int2 eb2 = g_edges[idx+2], eb3 = g_edges[idx+3];
            int2 eb4 = g_edges[idx+4], eb5 = g_edges[idx+5];
            int2 eb6 = g_edges[idx+6], eb7 = g_edges[idx+7];
            idx += 8;
            for (; idx < end8; idx += 8) {
                int2 n0 = g_edges[idx+0], n1 = g_edges[idx+1];
                int2 n2 = g_edges[idx+2], n3 = g_edges[idx+3];
                int2 n4 = g_edges[idx+4], n5 = g_edges[idx+5];
                int2 n6 = g_edges[idx+6], n7 = g_edges[idx+7];
                CONSUME8();
                eb0 = n0; eb1 = n1; eb2 = n2; eb3 = n3;
                eb4 = n4; eb5 = n5; eb6 = n6; eb7 = n7;
            }
            CONSUME8();
        }
        for (; idx < e; idx++) {
            int2 ed = g_edges[idx];
            float wt = __int_as_float(ed.y);
            float4 v = in4[ed.x * 32 + lane];
            acc.x += wt * v.x; acc.y += wt * v.y;
            acc.z += wt * v.z; acc.w += wt * v.w;
        }
        ((float4*)(As + wp * 128))[lane] = acc;
    }
    __syncthreads();
    // ---- GEMM phase: 1 row x 4 cols per thread, packed f32x2 FMAs ----
    int jg = tid & 31;                        // cols 4*jg .. 4*jg+3
    int rw = tid >> 5;                        // row within tile
    const float4* W4 = (const float4*)W;
    const float4* A4 = (const float4*)As;     // A4[row*32 + k4]
    unsigned long long p0, p1;
    {
        float z = 0.f;
        asm("mov.b64 %0,{%1,%1};" : "=l"(p0) : "f"(z));
        p1 = p0;
    }
    #pragma unroll 8
    for (int k4 = 0; k4 < 32; k4++) {
        float4 x = A4[rw * 32 + k4];
        #pragma unroll
        for (int kk = 0; kk < 4; kk++) {
            float xs = (kk == 0) ? x.x : (kk == 1) ? x.y : (kk == 2) ? x.z : x.w;
            float4 w = W4[(k4 * 4 + kk) * 32 + jg];
            unsigned long long w01, w23, xx;
            asm("mov.b64 %0,{%1,%2};" : "=l"(w01) : "f"(w.x), "f"(w.y));
            asm("mov.b64 %0,{%1,%2};" : "=l"(w23) : "f"(w.z), "f"(w.w));
            asm("mov.b64 %0,{%1,%1};" : "=l"(xx) : "f"(xs));
            asm("fma.rn.f32x2 %0,%1,%2,%0;" : "+l"(p0) : "l"(xx), "l"(w01));
            asm("fma.rn.f32x2 %0,%1,%2,%0;" : "+l"(p1) : "l"(xx), "l"(w23));
        }
    }
    float4 b = ((const float4*)bias)[jg];
    float c0, c1, c2, c3;
    asm("mov.b64 {%0,%1},%2;" : "=f"(c0), "=f"(c1) : "l"(p0));
    asm("mov.b64 {%0,%1},%2;" : "=f"(c2), "=f"(c3) : "l"(p1));
    int row = r0 + rw;
    ((float4*)out)[row * 32 + jg] = make_float4(
        fmaxf(c0 + b.x, 0.f), fmaxf(c1 + b.y, 0.f),
        fmaxf(c2 + b.z, 0.f), fmaxf(c3 + b.w, 0.f));
}

__device__ __forceinline__ float sigmoidf_(float x) { return 1.f / (1.f + __expf(-x)); }

// ---------------- fused LSTM-gates GEMM + nonlinearity (2 graphs / block, 256 blocks) ----------------
__global__ void __launch_bounds__(512) k_gates_lstm() {
    __shared__ float sA[2 * 384];     // [q_star | hs] inputs
    __shared__ float sg[2 * 512];     // gate pre-activations
    int tid = threadIdx.x;
    int gb = blockIdx.x;              // 0..255
    for (int idx = tid; idx < 2 * 384; idx += 512) {
        int g = idx / 384, k = idx % 384;
        int gg = gb * 2 + g;
        sA[idx] = (k < 256) ? g_qstar[gg * 256 + k] : g_hs[gg * 128 + (k - 256)];
    }
    __syncthreads();
    int j = tid;                      // 0..511 gate index
    float acc0 = 0.f, acc1 = 0.f;
    for (int k0 = 0; k0 < 384; k0 += 8) {
        float wv[8];
        #pragma unroll
        for (int u = 0; u < 8; u++) wv[u] = g_WT[(k0 + u) * 512 + j];
        #pragma unroll
        for (int u = 0; u < 8; u++) {
            acc0 += sA[k0 + u]       * wv[u];
            acc1 += sA[384 + k0 + u] * wv[u];
        }
    }
    float bb = g_gbias[j];
    sg[j]       = acc0 + bb;
    sg[512 + j] = acc1 + bb;
    __syncthreads();
    // LSTM cell update: 2 graphs x 128 dims = 256 items
    if (tid < 256) {
        int g = tid >> 7, jj = tid & 127;
        int gg = gb * 2 + g;
        const float* gr = &sg[g * 512];
        float ig = gr[jj], fg = gr[jj + 128], ga = gr[jj + 256], og = gr[jj + 384];
        int gidx = gg * 128 + jj;
        float c = sigmoidf_(fg) * g_cs[gidx] + sigmoidf_(ig) * tanhf(ga);
        g_cs[gidx] = c;
        float q = sigmoidf_(og) * tanhf(c);
        g_hs[gidx] = q;
        g_qstar[gg * 256 + jj] = q;   // q part of q_star
    }
}

// ---------------- attention (+ fused MLP head on the last step), block per graph ----------------
__global__ void __launch_bounds__(256) k_attn(
        const float* __restrict__ h, int do_mlp,
        const float* __restrict__ L1w, const float* __restrict__ L1b,
        const float* __restrict__ L2w, const float* __restrict__ L2b,
        const float* __restrict__ L3w, const float* __restrict__ L3b,
        float* __restrict__ out) {
    __shared__ float sq[128];
    __shared__ float swmax[8];
    __shared__ float semax;
    __shared__ float sr[256];
    __shared__ float sa[2];
    __shared__ float rfin[128];
    __shared__ float y1[128];
    __shared__ float y2[64];
    __shared__ float ys[NCLS];
    int g = blockIdx.x;
    int tid = threadIdx.x;
    int lane = tid & 31, warp = tid >> 5;
    if (tid < 128) sq[tid] = g_hs[g * 128 + tid];
    __syncthreads();
    int s = g_gptr[g], e = g_gptr[g + 1];
    if (s < e) {
        float lmax = -INFINITY;
        float4 qv = ((const float4*)sq)[lane];
        const float4* h4 = (const float4*)h;
        for (int i = s + warp; i < e; i += 8) {
            float4 hv = h4[i * 32 + lane];
            float d = hv.x * qv.x + hv.y * qv.y + hv.z * qv.z + hv.w * qv.w;
            #pragma unroll
            for (int o = 16; o > 0; o >>= 1) d += __shfl_xor_sync(0xffffffffu, d, o);
            if (lane == 0) g_escr[i] = d;
            lmax = fmaxf(lmax, d);
        }
        if (lane == 0) swmax[warp] = lmax;
        __syncthreads();
        if (tid == 0) {
            float m = swmax[0];
            #pragma unroll
            for (int w = 1; w < 8; w++) m = fmaxf(m, swmax[w]);
            semax = m;
        }
        __syncthreads();
        float emax = semax;
        int grp = tid >> 7, dim = tid & 127;
        int half = (e - s) >> 1;
        int b0 = (grp == 0) ? s : s + half;
        int b1 = (grp == 0) ? s + half : e;
        float r = 0.f, asum = 0.f;
        #pragma unroll 4
        for (int i = b0; i < b1; i++) {
            float w = __expf(g_escr[i] - emax);
            asum += w;
            r += w * h[i * 128 + dim];
        }
        sr[tid] = r;
        if (dim == 0) sa[grp] = asum;
        __syncthreads();
        if (tid < 128) {
            float rt = sr[tid] + sr[128 + tid];
            float at = sa[0] + sa[1];
            rfin[tid] = rt / (at > 0.f ? at : 1.f);
        }
    } else {
        if (tid < 128) rfin[tid] = 0.f;
    }
    __syncthreads();
    if (!do_mlp) {
        if (tid < 128) g_qstar[g * 256 + 128 + tid] = rfin[tid];
        return;
    }
    if (tid < 128) {
        float acc = L1b[tid];
        #pragma unroll 4
        for (int k = 0; k < 128; k++) acc += sq[k] * L1w[k * 128 + tid];
        #pragma unroll 4
        for (int k = 0; k < 128; k++) acc += rfin[k] * L1w[(128 + k) * 128 + tid];
        y1[tid] = fmaxf(acc, 0.f);
    }
    __syncthreads();
    if (tid < 64) {
        float acc = L2b[tid];
        #pragma unroll 4
        for (int k = 0; k < 128; k++) acc += y1[k] * L2w[k * 64 + tid];
        y2[tid] = fmaxf(acc, 0.f);
    }
    __syncthreads();
    if (tid < NCLS) {
        float acc = L3b[tid];
        #pragma unroll
        for (int k = 0; k < 64; k++) acc += y2[k] * L3w[k * NCLS + tid];
        ys[tid] = acc;
    }
    __syncthreads();
    if (tid < NCLS) {
        float m = ys[0];
        #pragma unroll
        for (int k = 1; k < NCLS; k++) m = fmaxf(m, ys[k]);
        float se = 0.f;
        #pragma unroll
        for (int k = 0; k < NCLS; k++) se += expf(ys[k] - m);
        out[g * NCLS + tid] = ys[tid] - m - logf(se);
    }
}

// ---------------- launcher ----------------
extern "C" void kernel_launch(void* const* d_in, const int* in_sizes, int n_in,
                              void* d_out, int out_size) {
    const float* x     = (const float*)d_in[0];
    const int*   ei    = (const int*)  d_in[1];
    const int*   batch = (const int*)  d_in[2];
    const float* W1 = (const float*)d_in[3];  const float* b1 = (const float*)d_in[4];
    const float* W2 = (const float*)d_in[5];  const float* b2 = (const float*)d_in[6];
    const float* W3 = (const float*)d_in[7];  const float* b3 = (const float*)d_in[8];
    const float* Wih = (const float*)d_in[9]; const float* Whh = (const float*)d_in[10];
    const float* bih = (const float*)d_in[11];const float* bhh = (const float*)d_in[12];
    const float* L1w = (const float*)d_in[13];const float* L1b = (const float*)d_in[14];
    const float* L2w = (const float*)d_in[15];const float* L2b = (const float*)d_in[16];
    const float* L3w = (const float*)d_in[17];const float* L3b = (const float*)d_in[18];
    float* out = (float*)d_out;

    int layer_grid = N_NODES / 8;   // 6250, exact

    k_hist<<<(N_EDGES + 255) / 256, 256>>>(ei);                           // 0
    k_scanA<<<SCAN_NB, 1024>>>();                                         // 1
    k_prep2<<<(384 * 512 + 255) / 256, 256>>>(batch, Wih, Whh, bih, bhh); // 2
    k_gates_lstm<<<256, 512>>>();                                         // 3  <- ncu capture (step 0)
    k_scanB<<<SCAN_NB, 1024>>>();                                         // 4
    k_fill<<<(N_EDGES + 255) / 256, 256>>>(ei);                           // 5

    k_layer<<<layer_grid, 256>>>(x,    W1, b1, g_hA);                     // 6
    k_layer<<<layer_grid, 256>>>(g_hA, W2, b2, g_hB);                     // 7
    k_layer<<<layer_grid, 256>>>(g_hB, W3, b3, g_hA);                     // 8

    k_attn<<<NGR, 256>>>(g_hA, 0, L1w, L1b, L2w, L2b, L3w, L3b, out);     // 9 (step 0 attn)
    for (int step = 1; step < 4; step++) {
        k_gates_lstm<<<256, 512>>>();
        k_attn<<<NGR, 256>>>(g_hA, step == 3 ? 1 : 0,
                             L1w, L1b, L2w, L2b, L3w, L3b, out);
    }
}